// round 3
// baseline (speedup 1.0000x reference)
#include <cuda_runtime.h>
#include <cuda_bf16.h>

// Problem constants
#define B_     32
#define CIN    64
#define H_     64
#define W_     64
#define COUT   128
#define CONN   4
#define KHW    9
#define RROWS  2              // output rows per block stripe
#define SROWS  (RROWS+2)      // 4 shared rows incl. halo (di in 0..2, pad_l=1)
#define WPAD   67             // 1 left halo + 64 data + 1 right halo + 1 pad (odd stride)
#define NTHREADS 512
#define NSTRIPES (H_ / RROWS) // 32

// Shared memory layout (bytes)
#define XS_FLOATS (CIN * SROWS * WPAD)      // 64*4*67 = 17152
#define XS_BYTES  (XS_FLOATS * 4)           // 68608
#define TBL_OFF   (XS_BYTES)                // float2[512] (w, offs) : 4096 B
#define BSH_OFF   (TBL_OFF + 4096)          // float[128] : 512 B
#define SMEM_TOTAL (BSH_OFF + 512)          // 73216 B  -> 3 CTAs/SM

__global__ void __launch_bounds__(NTHREADS, 3)
lp_conv2d_bt_kernel(const float* __restrict__ x,
                    const float* __restrict__ wts,
                    const float* __restrict__ bias,
                    const int*   __restrict__ conn,
                    float* __restrict__ out)
{
    extern __shared__ char smem[];
    float*  xs  = (float*)smem;
    float2* tbl = (float2*)(smem + TBL_OFF);
    float*  bsh = (float*)(smem + BSH_OFF);

    const int tid = threadIdx.x;
    const int s   = blockIdx.x;   // stripe 0..31
    const int b   = blockIdx.y;   // batch 0..31

    // ---- Stage conn table: 512 (o,j) entries, one per thread ----
    // Entry: w and precomputed float-offset into xs, with dj and left-halo folded in.
    {
        int idx = conn[tid];               // 0 .. CIN*KHW-1
        int c   = idx / KHW;
        int rem = idx - c * KHW;
        int di  = rem / 3;
        int dj  = rem - di * 3;
        // tap float index for (out-row ri, col): (c*SROWS + di + ri)*WPAD + (col + dj)
        float2 t;
        t.x = wts[tid];
        t.y = __uint_as_float((unsigned)((c * SROWS + di) * WPAD + dj));
        tbl[tid] = t;
        if (tid < COUT) bsh[tid] = bias[tid];
    }

    // ---- Load input stripe: 64 ch x SROWS rows (edge-clamped) into padded smem ----
    const int i0 = s * RROWS;
    const float4* __restrict__ xsrc =
        (const float4*)(x + (size_t)b * (CIN * H_ * W_));
    // total float4s: CIN*SROWS*(W_/4) = 4096 ; 8 per thread, gmem-coalesced
    #pragma unroll
    for (int it = 0; it < (CIN * SROWS * (W_/4)) / NTHREADS; it++) {
        int idx = tid + it * NTHREADS;
        int ch  = idx >> 6;                 // 64 float4 per channel (16/row * 4 rows)
        int rem = idx & 63;
        int r   = rem >> 4;                 // shared row 0..3
        int c4  = rem & 15;
        int gr  = i0 - 1 + r;
        gr = max(0, min(H_ - 1, gr));       // edge padding = clamp
        float4 v = xsrc[(ch * H_ + gr) * (W_/4) + c4];
        float* dst = xs + (ch * SROWS + r) * WPAD + 1 + c4 * 4;  // data at [1..64]
        dst[0] = v.x; dst[1] = v.y; dst[2] = v.z; dst[3] = v.w;
        if (c4 == 0)  dst[-1] = v.x;        // left halo  = col 0
        if (c4 == 15) dst[4]  = v.w;        // right halo = col 63
    }
    __syncthreads();

    // ---- Compute: lane = column, slot picks o-subset, 2 rows per thread ----
    const int col  = tid & 63;
    const int slot = tid >> 6;             // 0..7

    float* outbase = out + (((size_t)b * COUT) * H_ + i0) * W_ + col;
    const float* xcol = xs + col;

    #pragma unroll 4
    for (int k = 0; k < 16; k++) {
        const int o = slot * 16 + k;       // all 128 o covered across slots
        float m0 = 0.0f, m1 = 0.0f;        // |diff| >= 0 -> 0-init safe
        #pragma unroll
        for (int j = 0; j < CONN; j++) {
            const float2 t = tbl[o * CONN + j];     // broadcast LDS.64
            const float* p = xcol + __float_as_uint(t.y);
            const float w  = t.x;
            m0 = fmaxf(m0, fabsf(w - p[0]));        // out row i0   (shared r = di)
            m1 = fmaxf(m1, fabsf(w - p[WPAD]));     // out row i0+1 (shared r = di+1)
        }
        const float bv = bsh[o];
        float* po = outbase + (size_t)o * (H_ * W_);
        po[0]  = m0 + bv;
        po[W_] = m1 + bv;
    }
}

extern "C" void kernel_launch(void* const* d_in, const int* in_sizes, int n_in,
                              void* d_out, int out_size)
{
    const float* x    = (const float*)d_in[0];   // [32,64,64,64]
    const float* wts  = (const float*)d_in[1];   // [128,4]
    const float* bias = (const float*)d_in[2];   // [128,1,1]
    const int*   conn = (const int*)d_in[3];     // [128,4] int32
    float* out = (float*)d_out;                  // [32,128,64,64]

    static_assert(SMEM_TOTAL <= 227 * 1024, "smem");
    cudaFuncSetAttribute(lp_conv2d_bt_kernel,
                         cudaFuncAttributeMaxDynamicSharedMemorySize, SMEM_TOTAL);

    dim3 grid(NSTRIPES, B_);
    lp_conv2d_bt_kernel<<<grid, NTHREADS, SMEM_TOTAL>>>(x, wts, bias, conn, out);
}

// round 5
// speedup vs baseline: 1.0198x; 1.0198x over previous
#include <cuda_runtime.h>
#include <cuda_bf16.h>

// Problem constants
#define B_     32
#define CIN    64
#define H_     64
#define W_     64
#define COUT   128
#define CONN   4
#define KHW    9
#define RROWS  4              // output rows per block stripe
#define SROWS  (RROWS+2)      // 6 shared rows incl. halo (di in 0..2, pad_l=1)
#define WPAD   72             // row stride: [3]=left halo, [4..67]=cols 0..63, [68]=right halo
#define NTHREADS 512
#define NSTRIPES (H_ / RROWS) // 16

// Dynamic shared memory: input stripe only (tables live in __constant__)
#define XS_FLOATS  (CIN * SROWS * WPAD)     // 64*6*72 = 27648
#define SMEM_TOTAL (XS_FLOATS * 4)          // 110592 B -> 2 CTAs/SM

// Decoded tap table: (w, float-offset) per (o,j), and bias — uniform across blocks.
__constant__ float2 c_tbl[COUT * CONN];     // 4 KB
__constant__ float  c_bias[COUT];           // 512 B
__device__ float2 g_tbl[COUT * CONN];
__device__ float  g_bias[COUT];

__global__ void decode_kernel(const float* __restrict__ wts,
                              const float* __restrict__ bias,
                              const int*   __restrict__ conn)
{
    const int tid = threadIdx.x;            // 0..511
    int idx = conn[tid];                    // 0 .. CIN*KHW-1
    int c   = idx / KHW;
    int rem = idx - c * KHW;
    int di  = rem / 3;
    int dj  = rem - di * 3;
    float2 t;
    t.x = wts[tid];
    // float offset into xs for (out-row 0, col 0): xs[off + col + ri*WPAD]
    t.y = __uint_as_float((unsigned)((c * SROWS + di) * WPAD + dj + 3));
    g_tbl[tid] = t;
    if (tid < COUT) g_bias[tid] = bias[tid];
}

__global__ void __launch_bounds__(NTHREADS, 2)
lp_conv2d_bt_kernel(const float* __restrict__ x,
                    float* __restrict__ out)
{
    extern __shared__ float xs[];

    const int tid = threadIdx.x;
    const int s   = blockIdx.x;   // stripe 0..15
    const int b   = blockIdx.y;   // batch 0..31

    // ---- Load input stripe: 64 ch x 6 rows (edge-clamped) into padded smem ----
    const int i0 = s * RROWS;
    const float4* __restrict__ xsrc =
        (const float4*)(x + (size_t)b * (CIN * H_ * W_));
    // total float4s: CIN*SROWS*(W_/4) = 6144 ; 12 per thread, gmem-coalesced
    #pragma unroll
    for (int it = 0; it < (CIN * SROWS * (W_/4)) / NTHREADS; it++) {
        int idx = tid + it * NTHREADS;
        int ch  = idx / (SROWS * (W_/4));       // /96
        int rem = idx - ch * (SROWS * (W_/4));
        int r   = rem >> 4;                     // shared row 0..5
        int c4  = rem & 15;
        int gr  = i0 - 1 + r;
        gr = max(0, min(H_ - 1, gr));           // edge padding = row clamp
        float4 v = xsrc[(ch * H_ + gr) * (W_/4) + c4];
        float* row = xs + (ch * SROWS + r) * WPAD;
        *(float4*)(row + 4 + c4 * 4) = v;       // aligned STS.128
        if (c4 == 0)  row[3]  = v.x;            // left  halo = col 0
        if (c4 == 15) row[68] = v.w;            // right halo = col 63
    }
    __syncthreads();

    // ---- Compute: lane = column, slot picks o-subset, 4 rows per thread ----
    const int col  = tid & 63;
    const int slot = tid >> 6;                  // 0..7

    float* outbase = out + (((size_t)b * COUT) * H_ + i0) * W_ + col;
    const float* xcol = xs + col;
    const float4* tt = (const float4*)c_tbl;    // (w0,off0,w1,off1) pairs

    #pragma unroll 4
    for (int k = 0; k < 16; k++) {
        const int o = slot * 16 + k;            // all 128 o covered across slots
        float m0 = 0.0f, m1 = 0.0f, m2 = 0.0f, m3 = 0.0f;   // |diff|>=0 -> safe
        #pragma unroll
        for (int jj = 0; jj < 2; jj++) {
            const float4 t = tt[o * 2 + jj];    // LDC.128: taps 2jj, 2jj+1
            {
                const float w = t.x;
                const float* p = xcol + __float_as_uint(t.y);
                m0 = fmaxf(m0, fabsf(w - p[0 * WPAD]));
                m1 = fmaxf(m1, fabsf(w - p[1 * WPAD]));
                m2 = fmaxf(m2, fabsf(w - p[2 * WPAD]));
                m3 = fmaxf(m3, fabsf(w - p[3 * WPAD]));
            }
            {
                const float w = t.z;
                const float* p = xcol + __float_as_uint(t.w);
                m0 = fmaxf(m0, fabsf(w - p[0 * WPAD]));
                m1 = fmaxf(m1, fabsf(w - p[1 * WPAD]));
                m2 = fmaxf(m2, fabsf(w - p[2 * WPAD]));
                m3 = fmaxf(m3, fabsf(w - p[3 * WPAD]));
            }
        }
        const float bv = c_bias[o];
        float* po = outbase + (size_t)o * (H_ * W_);
        __stcs(po + 0 * W_, m0 + bv);           // streaming: keep x resident in L2
        __stcs(po + 1 * W_, m1 + bv);
        __stcs(po + 2 * W_, m2 + bv);
        __stcs(po + 3 * W_, m3 + bv);
    }
}

extern "C" void kernel_launch(void* const* d_in, const int* in_sizes, int n_in,
                              void* d_out, int out_size)
{
    const float* x    = (const float*)d_in[0];   // [32,64,64,64]
    const float* wts  = (const float*)d_in[1];   // [128,4]
    const float* bias = (const float*)d_in[2];   // [128,1,1]
    const int*   conn = (const int*)d_in[3];     // [128,4] int32
    float* out = (float*)d_out;                  // [32,128,64,64]

    decode_kernel<<<1, NTHREADS>>>(wts, bias, conn);

    void* p_tbl = nullptr; void* p_bias = nullptr;
    cudaGetSymbolAddress(&p_tbl,  g_tbl);
    cudaGetSymbolAddress(&p_bias, g_bias);
    cudaMemcpyToSymbolAsync(c_tbl,  p_tbl,  sizeof(float2) * COUT * CONN, 0,
                            cudaMemcpyDeviceToDevice);
    cudaMemcpyToSymbolAsync(c_bias, p_bias, sizeof(float) * COUT, 0,
                            cudaMemcpyDeviceToDevice);

    cudaFuncSetAttribute(lp_conv2d_bt_kernel,
                         cudaFuncAttributeMaxDynamicSharedMemorySize, SMEM_TOTAL);

    dim3 grid(NSTRIPES, B_);
    lp_conv2d_bt_kernel<<<grid, NTHREADS, SMEM_TOTAL>>>(x, out);
}

// round 6
// speedup vs baseline: 1.0914x; 1.0703x over previous
#include <cuda_runtime.h>
#include <cuda_bf16.h>

// Problem constants
#define B_     32
#define CIN    64
#define H_     64
#define W_     64
#define COUT   128
#define CONN   4
#define KHW    9
#define RROWS  4              // output rows per block stripe
#define SROWS  (RROWS+2)      // 6 shared rows incl. halo (di in 0..2)
#define NTHREADS 512
#define NSTRIPES (H_ / RROWS) // 16

// Even/odd split row layout (floats), stride RS per (ch,row):
//   [0..31]  = even cols 0,2,..,62
//   [32]     = halo copy of col 63   (for col-64 clamp)
//   [33]     = halo copy of col 0    (for col -1 clamp)
//   [34..65] = odd cols 1,3,..,63
#define RS     66

#define XS_FLOATS (CIN * SROWS * RS)        // 64*6*66 = 25344
#define XS_BYTES  (XS_FLOATS * 4)           // 101376
#define TBL_OFF   (XS_BYTES)                // float4[512]: 8192 B
#define BSH_OFF   (TBL_OFF + 8192)          // float[128]: 512 B
#define SMEM_TOTAL (BSH_OFF + 512)          // 110080 B -> 2 CTAs/SM

__global__ void __launch_bounds__(NTHREADS, 2)
lp_conv2d_bt_kernel(const float* __restrict__ x,
                    const float* __restrict__ wts,
                    const float* __restrict__ bias,
                    const int*   __restrict__ conn,
                    float* __restrict__ out)
{
    extern __shared__ float xs[];
    float4* tbl = (float4*)((char*)xs + TBL_OFF);
    float*  bsh = (float*)((char*)xs + BSH_OFF);

    const int tid = threadIdx.x;
    const int s   = blockIdx.x;   // stripe 0..15
    const int b   = blockIdx.y;   // batch 0..31

    // ---- Decode conn table: 512 (o,j) entries, one per thread ----
    // Tap column for output col c (=2g or 2g+1) is c+dj-1 clamped to [0,63];
    // plane offsets fold parity + halo clamping:
    //   elem0 (col 2g):   dj=0 -> odd[g-1] (33+g, g=0 hits haloL)
    //                     dj=1 -> even[g]  (0+g)
    //                     dj=2 -> odd[g]   (34+g)
    //   elem1 (col 2g+1): dj=0 -> even[g]  (0+g)
    //                     dj=1 -> odd[g]   (34+g)
    //                     dj=2 -> even[g+1](1+g, g=31 hits haloR)
    {
        int idx = conn[tid];               // 0 .. CIN*KHW-1
        int c   = idx / KHW;
        int rem = idx - c * KHW;
        int di  = rem / 3;
        int dj  = rem - di * 3;
        int base = (c * SROWS + di) * RS;
        int o0 = (dj == 0) ? 33 : (dj == 1 ? 0 : 34);
        int o1 = (dj == 0) ? 0  : (dj == 1 ? 34 : 1);
        float4 t;
        t.x = wts[tid];
        t.y = __uint_as_float((unsigned)(base + o0));
        t.z = __uint_as_float((unsigned)(base + o1));
        t.w = 0.0f;
        tbl[tid] = t;
        if (tid < COUT) bsh[tid] = bias[tid];
    }

    // ---- Stage input stripe: 64 ch x 6 rows (edge-clamped) into split layout ----
    const int i0 = s * RROWS;
    const float4* __restrict__ xsrc =
        (const float4*)(x + (size_t)b * (CIN * H_ * W_));
    // total float4s: CIN*SROWS*(W_/4) = 6144 ; 12 per thread, gmem-coalesced
    #pragma unroll
    for (int it = 0; it < (CIN * SROWS * (W_/4)) / NTHREADS; it++) {
        int idx = tid + it * NTHREADS;
        int ch  = idx / (SROWS * (W_/4));       // /96
        int rem = idx - ch * (SROWS * (W_/4));
        int r   = rem >> 4;                     // shared row 0..5
        int c4  = rem & 15;                     // float4 group: cols 4c4..4c4+3
        int gr  = i0 - 1 + r;
        gr = max(0, min(H_ - 1, gr));           // edge padding = row clamp
        float4 v = xsrc[(ch * H_ + gr) * (W_/4) + c4];
        float* row = xs + (ch * SROWS + r) * RS;
        // evens -> even plane, odds -> odd plane (both 8B-aligned STS.64)
        *(float2*)(row + 2 * c4)      = make_float2(v.x, v.z);
        *(float2*)(row + 34 + 2 * c4) = make_float2(v.y, v.w);
        if (c4 == 0)  row[33] = v.x;            // haloL = col 0
        if (c4 == 15) row[32] = v.w;            // haloR = col 63
    }
    __syncthreads();

    // ---- Compute: lane = col-pair, warp = slot of 8 o's, 2 cols x 4 rows / o ----
    const int g    = tid & 31;                  // col pair: cols 2g, 2g+1
    const int slot = tid >> 5;                  // 0..15, o in [slot*8, slot*8+8)

    const float* xg = xs + g;
    float* outbase = out + (((size_t)(b * COUT + slot * 8)) * H_ + i0) * W_ + 2 * g;

    #pragma unroll 2
    for (int k = 0; k < 8; k++) {
        const int o = slot * 8 + k;
        float m00 = 0.f, m01 = 0.f, m10 = 0.f, m11 = 0.f;
        float m20 = 0.f, m21 = 0.f, m30 = 0.f, m31 = 0.f;   // |diff|>=0 -> safe
        #pragma unroll
        for (int j = 0; j < CONN; j++) {
            const float4 t = tbl[o * CONN + j];             // broadcast LDS.128
            const float w  = t.x;
            const float* p0 = xg + __float_as_uint(t.y);    // elem0 plane
            const float* p1 = xg + __float_as_uint(t.z);    // elem1 plane
            m00 = fmaxf(m00, fabsf(w - p0[0 * RS]));
            m01 = fmaxf(m01, fabsf(w - p1[0 * RS]));
            m10 = fmaxf(m10, fabsf(w - p0[1 * RS]));
            m11 = fmaxf(m11, fabsf(w - p1[1 * RS]));
            m20 = fmaxf(m20, fabsf(w - p0[2 * RS]));
            m21 = fmaxf(m21, fabsf(w - p1[2 * RS]));
            m30 = fmaxf(m30, fabsf(w - p0[3 * RS]));
            m31 = fmaxf(m31, fabsf(w - p1[3 * RS]));
        }
        const float bv = bsh[o];
        float* po = outbase + (size_t)k * (H_ * W_);
        *(float2*)(po + 0 * W_) = make_float2(m00 + bv, m01 + bv);  // STG.64
        *(float2*)(po + 1 * W_) = make_float2(m10 + bv, m11 + bv);
        *(float2*)(po + 2 * W_) = make_float2(m20 + bv, m21 + bv);
        *(float2*)(po + 3 * W_) = make_float2(m30 + bv, m31 + bv);
    }
}

extern "C" void kernel_launch(void* const* d_in, const int* in_sizes, int n_in,
                              void* d_out, int out_size)
{
    const float* x    = (const float*)d_in[0];   // [32,64,64,64]
    const float* wts  = (const float*)d_in[1];   // [128,4]
    const float* bias = (const float*)d_in[2];   // [128,1,1]
    const int*   conn = (const int*)d_in[3];     // [128,4] int32
    float* out = (float*)d_out;                  // [32,128,64,64]

    static_assert(SMEM_TOTAL <= 227 * 1024 / 2, "want 2 CTAs/SM");
    cudaFuncSetAttribute(lp_conv2d_bt_kernel,
                         cudaFuncAttributeMaxDynamicSharedMemorySize, SMEM_TOTAL);

    dim3 grid(NSTRIPES, B_);
    lp_conv2d_bt_kernel<<<grid, NTHREADS, SMEM_TOTAL>>>(x, wts, bias, conn, out);
}